// round 11
// baseline (speedup 1.0000x reference)
#include <cuda_runtime.h>

typedef unsigned long long u64;

#define T_SEQ 34
#define RWS 16          // rows per block
#define TH 17           // paired positions: thread t handles t and 33-t
#define NT (RWS * TH)   // 272 threads
#define VCB 14

// ---- constant-packed weights (float2) ----
//  54 N(36,dup): fused outw·vw   | 90 w1(18,dup) | 108 w2(18,dup)
//  126 b1(3) | 129 b2(6) | 147 l2g 153 l2b 159 lfg 165 lfb
//  171 wlog(84,dup)   -> total 255
#define NPK 255
__constant__ __align__(8) float2 c_pack[NPK];
__device__ __align__(8) float2 g_scratch[NPK];
// per-(t,tok) table: [u00,u10,u01,u11,u02,u12, h3,h4,h5, h0,h1,h2] = 48B
__device__ __align__(16) float g_table[T_SEQ * VCB * 12];

__device__ __forceinline__ u64 pk2(float lo, float hi) {
    u64 r; asm("mov.b64 %0, {%1, %2};" : "=l"(r) : "f"(lo), "f"(hi)); return r;
}
__device__ __forceinline__ void up2(u64 v, float& a, float& b) {
    asm("mov.b64 {%0, %1}, %2;" : "=f"(a), "=f"(b) : "l"(v));
}
__device__ __forceinline__ u64 f2fma(u64 a, u64 b, u64 c) {
    u64 d; asm("fma.rn.f32x2 %0, %1, %2, %3;" : "=l"(d) : "l"(a), "l"(b), "l"(c)); return d;
}
__device__ __forceinline__ u64 f2add(u64 a, u64 b) {
    u64 d; asm("add.rn.f32x2 %0, %1, %2;" : "=l"(d) : "l"(a), "l"(b)); return d;
}
__device__ __forceinline__ u64 f2mul(u64 a, u64 b) {
    u64 d; asm("mul.rn.f32x2 %0, %1, %2;" : "=l"(d) : "l"(a), "l"(b)); return d;
}
__device__ __forceinline__ float ex2(float x) {
    float y; asm("ex2.approx.f32 %0, %1;" : "=f"(y) : "f"(x)); return y;
}
__device__ __forceinline__ u64 cw(int i) {
    return *reinterpret_cast<const u64*>(&c_pack[i]);
}

// packed LayerNorm over 6 dims; lanes = two independent tokens
__device__ __forceinline__ void ln6p(const u64* x, int gi, int bi, u64* o) {
    u64 s = f2add(f2add(f2add(x[0], x[1]), f2add(x[2], x[3])), f2add(x[4], x[5]));
    u64 negmu = f2mul(s, pk2(-1.0f / 6.0f, -1.0f / 6.0f));
    u64 d0 = f2add(x[0], negmu), d1 = f2add(x[1], negmu), d2 = f2add(x[2], negmu);
    u64 d3 = f2add(x[3], negmu), d4 = f2add(x[4], negmu), d5 = f2add(x[5], negmu);
    u64 v = f2mul(d0, d0);
    v = f2fma(d1, d1, v); v = f2fma(d2, d2, v);
    v = f2fma(d3, d3, v); v = f2fma(d4, d4, v); v = f2fma(d5, d5, v);
    float va, vb; up2(v, va, vb);
    float ia = rsqrtf(va * (1.0f / 6.0f) + 1e-5f);
    float ib = rsqrtf(vb * (1.0f / 6.0f) + 1e-5f);
    u64 inv = pk2(ia, ib);
    o[0] = f2fma(f2mul(d0, inv), cw(gi + 0), cw(bi + 0));
    o[1] = f2fma(f2mul(d1, inv), cw(gi + 1), cw(bi + 1));
    o[2] = f2fma(f2mul(d2, inv), cw(gi + 2), cw(bi + 2));
    o[3] = f2fma(f2mul(d3, inv), cw(gi + 3), cw(bi + 3));
    o[4] = f2fma(f2mul(d4, inv), cw(gi + 4), cw(bi + 4));
    o[5] = f2fma(f2mul(d5, inv), cw(gi + 5), cw(bi + 5));
}

__global__ void prep_kernel(
    const float* __restrict__ tok_emb, const float* __restrict__ pos_enc,
    const float* __restrict__ qw, const float* __restrict__ kw, const float* __restrict__ vw,
    const float* __restrict__ outw,
    const float* __restrict__ ln1g, const float* __restrict__ ln1b,
    const float* __restrict__ ln2g, const float* __restrict__ ln2b,
    const float* __restrict__ lnfg, const float* __restrict__ lnfb,
    const float* __restrict__ fw1, const float* __restrict__ fb1,
    const float* __restrict__ fw2, const float* __restrict__ fb2,
    const float* __restrict__ headw)
{
    int i = threadIdx.x;
    const float qscale = 0.57735026918962576f * 1.4426950408889634f;  // rs3 * log2(e)

    if (i < NPK) {
        float lo = 0.f, hi = 0.f;
        if (i >= 54 && i < 90) {          // N[d][o=h*3+c] = sum_k outw[d][h3+k]*vw[h3+k][c]
            int d = (i - 54) / 6, o = (i - 54) % 6;
            int h = o / 3, c = o % 3;
            float n = 0.f;
            for (int k = 0; k < 3; k++)
                n += outw[d * 6 + h * 3 + k] * vw[(h * 3 + k) * 3 + c];
            lo = n; hi = n;
        }
        else if (i >= 90 && i < 108)  { lo = fw1[i - 90]; hi = lo; }
        else if (i >= 108 && i < 126) { lo = fw2[i - 108]; hi = lo; }
        else if (i >= 126 && i < 129) { lo = fb1[i - 126]; hi = lo; }
        else if (i >= 129 && i < 135) { lo = fb2[i - 129]; hi = lo; }
        else if (i >= 147 && i < 153) { lo = ln2g[i - 147]; hi = lo; }
        else if (i >= 153 && i < 159) { lo = ln2b[i - 153]; hi = lo; }
        else if (i >= 159 && i < 165) { lo = lnfg[i - 159]; hi = lo; }
        else if (i >= 165 && i < 171) { lo = lnfb[i - 165]; hi = lo; }
        else if (i >= 171) {
            int v = (i - 171) / 6, d = (i - 171) % 6;
            lo = tok_emb[v * 3 + 0] * headw[0 * 6 + d]
               + tok_emb[v * 3 + 1] * headw[1 * 6 + d]
               + tok_emb[v * 3 + 2] * headw[2 * 6 + d];
            hi = lo;
        }
        g_scratch[i] = make_float2(lo, hi);
    }

    int ti = i - 512;
    if (ti >= 0 && ti < T_SEQ * VCB) {
        int tt = ti / VCB, tok = ti % VCB;
        float x[6];
        x[0] = tok_emb[tok * 3 + 0]; x[1] = tok_emb[tok * 3 + 1]; x[2] = tok_emb[tok * 3 + 2];
        x[3] = pos_enc[tt * 3 + 0];  x[4] = pos_enc[tt * 3 + 1];  x[5] = pos_enc[tt * 3 + 2];
        float mu = 0.f;
        for (int d = 0; d < 6; d++) mu += x[d];
        mu *= (1.0f / 6.0f);
        float var = 0.f;
        for (int d = 0; d < 6; d++) { float dd = x[d] - mu; var += dd * dd; }
        var *= (1.0f / 6.0f);
        float inv = rsqrtf(var + 1e-5f);
        float h[6];
        for (int d = 0; d < 6; d++) h[d] = (x[d] - mu) * inv * ln1g[d] + ln1b[d];
        // u_h[c] = sum_d h_pos[d] * M_h[d][c],  M_h[d][c] = sum_k qw[h3+k][d]*kw[h3+k][c]*qscale
        float u[2][3];
        for (int hh = 0; hh < 2; hh++)
            for (int c = 0; c < 3; c++) {
                float m = 0.f;
                for (int d = 0; d < 3; d++) {
                    float mm = 0.f;
                    for (int k = 0; k < 3; k++)
                        mm += qw[(hh * 3 + k) * 3 + d] * kw[(hh * 3 + k) * 3 + c];
                    m += h[3 + d] * mm;
                }
                u[hh][c] = m * qscale;
            }
        float* e = g_table + ti * 12;
        e[0] = u[0][0]; e[1] = u[1][0]; e[2] = u[0][1];
        e[3] = u[1][1]; e[4] = u[0][2]; e[5] = u[1][2];
        e[6] = h[3]; e[7] = h[4]; e[8] = h[5];
        e[9] = h[0]; e[10] = h[1]; e[11] = h[2];
    }
}

__global__ __launch_bounds__(NT, 5) void add_tf_kernel(
    const int* __restrict__ idx,
    const float* __restrict__ tok_emb, const float* __restrict__ pos_enc,
    float* __restrict__ out)
{
    __shared__ float s_te[42], s_pe[102];
    __shared__ int s_idx[RWS * T_SEQ];
    // attention buffers and output staging live in disjoint phases -> union
    __shared__ union {
        struct {
            float4 hk[RWS][35];   // (h0,h1,h2,x0) per j
            float2 hx[RWS][35];   // (x1,x2) per j
        } att;
        float ob[RWS * T_SEQ * VCB];   // 7616 floats
    } uni;

    const int r = threadIdx.x;      // row in block (0..15)
    const int t = threadIdx.y;      // pair index (0..16)
    const int tid = t * RWS + r;

    for (int i = tid; i < 42; i += NT) s_te[i] = tok_emb[i];
    for (int i = tid; i < 102; i += NT) s_pe[i] = pos_enc[i];
    {
        const int4* gsrc = (const int4*)(idx + (size_t)blockIdx.x * (RWS * T_SEQ));
        int4* sdst = (int4*)s_idx;
        for (int i = tid; i < (RWS * T_SEQ) / 4; i += NT) sdst[i] = gsrc[i];
    }
    __syncthreads();

    const int tA = t, tB = 33 - t;
    const int tokA = s_idx[r * T_SEQ + tA];
    const int tokB = s_idx[r * T_SEQ + tB];

    // ---- prologue via (t,tok) lookup table: u + staged h/x ----
    u64 uA0, uA1, uA2, uB0, uB1, uB2;
    {
        const float4* eA = (const float4*)(g_table + (tA * VCB + tokA) * 12);
        float4 a0 = __ldg(eA), a1 = __ldg(eA + 1), a2 = __ldg(eA + 2);
        uA0 = pk2(a0.x, a0.y); uA1 = pk2(a0.z, a0.w); uA2 = pk2(a1.x, a1.y);
        uni.att.hk[r][tA] = make_float4(a1.z, a1.w, a2.x, a2.y);
        uni.att.hx[r][tA] = make_float2(a2.z, a2.w);

        const float4* eB = (const float4*)(g_table + (tB * VCB + tokB) * 12);
        float4 b0 = __ldg(eB), b1 = __ldg(eB + 1), b2 = __ldg(eB + 2);
        uB0 = pk2(b0.x, b0.y); uB1 = pk2(b0.z, b0.w); uB2 = pk2(b1.x, b1.y);
        uni.att.hk[r][tB] = make_float4(b1.z, b1.w, b2.x, b2.y);
        uni.att.hx[r][tB] = make_float2(b2.z, b2.w);
    }
    __syncthreads();

    // ---- causal attention: s_h = u_h . h_j ; accumulate sum(e), sum(e * x_tok) ----
    u64 ssA = 0ULL, aA0 = 0ULL, aA1 = 0ULL, aA2 = 0ULL;
    u64 ssB = 0ULL, aB0 = 0ULL, aB1 = 0ULL, aB2 = 0ULL;
    const float4* ph = uni.att.hk[r];
    const float2* px = uni.att.hx[r];
#pragma unroll 2
    for (int j = 0; j <= t; j++) {
        float4 H = ph[j]; float2 X = px[j];
        u64 hh0 = pk2(H.x, H.x), hh1 = pk2(H.y, H.y), hh2 = pk2(H.z, H.z);
        u64 xx0 = pk2(H.w, H.w), xx1 = pk2(X.x, X.x), xx2 = pk2(X.y, X.y);

        u64 sB = f2fma(uB2, hh2, f2fma(uB1, hh1, f2mul(uB0, hh0)));
        float sb0, sb1; up2(sB, sb0, sb1);
        u64 eB = pk2(ex2(sb0), ex2(sb1));
        ssB = f2add(ssB, eB);
        aB0 = f2fma(eB, xx0, aB0); aB1 = f2fma(eB, xx1, aB1); aB2 = f2fma(eB, xx2, aB2);

        u64 sA = f2fma(uA2, hh2, f2fma(uA1, hh1, f2mul(uA0, hh0)));
        float sa0, sa1; up2(sA, sa0, sa1);
        u64 eA = pk2(ex2(sa0), ex2(sa1));
        ssA = f2add(ssA, eA);
        aA0 = f2fma(eA, xx0, aA0); aA1 = f2fma(eA, xx1, aA1); aA2 = f2fma(eA, xx2, aA2);
    }
#pragma unroll 2
    for (int j = t + 1; j <= tB; j++) {
        float4 H = ph[j]; float2 X = px[j];
        u64 hh0 = pk2(H.x, H.x), hh1 = pk2(H.y, H.y), hh2 = pk2(H.z, H.z);
        u64 xx0 = pk2(H.w, H.w), xx1 = pk2(X.x, X.x), xx2 = pk2(X.y, X.y);

        u64 sB = f2fma(uB2, hh2, f2fma(uB1, hh1, f2mul(uB0, hh0)));
        float sb0, sb1; up2(sB, sb0, sb1);
        u64 eB = pk2(ex2(sb0), ex2(sb1));
        ssB = f2add(ssB, eB);
        aB0 = f2fma(eB, xx0, aB0); aB1 = f2fma(eB, xx1, aB1); aB2 = f2fma(eB, xx2, aB2);
    }
    __syncthreads();   // att -> ob buffer reuse

    // normalize head-packed x-sums; out-proj (N = outw·vw folded) happens below
    u64 o2[6];
    {
        float s0, s1; up2(ssA, s0, s1);
        u64 invA = pk2(__fdividef(1.0f, s0), __fdividef(1.0f, s1));
        up2(ssB, s0, s1);
        u64 invB = pk2(__fdividef(1.0f, s0), __fdividef(1.0f, s1));
        aA0 = f2mul(aA0, invA); aA1 = f2mul(aA1, invA); aA2 = f2mul(aA2, invA);
        aB0 = f2mul(aB0, invB); aB1 = f2mul(aB1, invB); aB2 = f2mul(aB2, invB);

        float oA[6], oB[6];
        up2(aA0, oA[0], oA[3]); up2(aA1, oA[1], oA[4]); up2(aA2, oA[2], oA[5]);
        up2(aB0, oB[0], oB[3]); up2(aB1, oB[1], oB[4]); up2(aB2, oB[2], oB[5]);
#pragma unroll
        for (int o = 0; o < 6; o++) o2[o] = pk2(oA[o], oB[o]);
    }

    // rebuild x2 (cheap; kept regs low through the loop)
    u64 xa[6];
    xa[0] = pk2(s_te[tokA * 3 + 0], s_te[tokB * 3 + 0]);
    xa[1] = pk2(s_te[tokA * 3 + 1], s_te[tokB * 3 + 1]);
    xa[2] = pk2(s_te[tokA * 3 + 2], s_te[tokB * 3 + 2]);
    xa[3] = pk2(s_pe[tA * 3 + 0], s_pe[tB * 3 + 0]);
    xa[4] = pk2(s_pe[tA * 3 + 1], s_pe[tB * 3 + 1]);
    xa[5] = pk2(s_pe[tA * 3 + 2], s_pe[tB * 3 + 2]);

    // fused (outw·vw) projection + residual
#pragma unroll
    for (int d = 0; d < 6; d++) {
        u64 a = xa[d];
#pragma unroll
        for (int o = 0; o < 6; o++) a = f2fma(o2[o], cw(54 + d * 6 + o), a);
        xa[d] = a;
    }

    // FFN (exact GELU) + residual
    {
        u64 h2[6];
        ln6p(xa, 147, 153, h2);
        u64 g2[3];
#pragma unroll
        for (int f = 0; f < 3; f++) {
            u64 u = cw(126 + f);
#pragma unroll
            for (int d = 0; d < 6; d++) u = f2fma(h2[d], cw(90 + f * 6 + d), u);
            float ua, ub; up2(u, ua, ub);
            float ga = 0.5f * ua * (1.0f + erff(ua * 0.70710678118654752f));
            float gb = 0.5f * ub * (1.0f + erff(ub * 0.70710678118654752f));
            g2[f] = pk2(ga, gb);
        }
#pragma unroll
        for (int d = 0; d < 6; d++) {
            u64 y = cw(129 + d);
#pragma unroll
            for (int f = 0; f < 3; f++) y = f2fma(g2[f], cw(108 + d * 3 + f), y);
            xa[d] = f2add(xa[d], y);
        }
    }

    // final LN + fused logits -> smem staging (float2 stores)
    u64 xf[6];
    ln6p(xa, 159, 165, xf);

    float2* soA = (float2*)&uni.ob[(r * T_SEQ + tA) * VCB];
    float2* soB = (float2*)&uni.ob[(r * T_SEQ + tB) * VCB];
#pragma unroll
    for (int v = 0; v < VCB; v += 2) {
        u64 acc0 = f2mul(xf[0], cw(171 + v * 6 + 0));
        u64 acc1 = f2mul(xf[0], cw(171 + (v + 1) * 6 + 0));
#pragma unroll
        for (int d = 1; d < 6; d++) {
            acc0 = f2fma(xf[d], cw(171 + v * 6 + d), acc0);
            acc1 = f2fma(xf[d], cw(171 + (v + 1) * 6 + d), acc1);
        }
        float a0, b0, a1, b1;
        up2(acc0, a0, b0); up2(acc1, a1, b1);
        soA[v / 2] = make_float2(a0, a1);
        soB[v / 2] = make_float2(b0, b1);
    }
    __syncthreads();

    // coalesced block-contiguous output write
    float4* dst = (float4*)(out + (size_t)blockIdx.x * (RWS * T_SEQ * VCB));
    const float4* src = (const float4*)uni.ob;
#pragma unroll
    for (int i = tid; i < (RWS * T_SEQ * VCB) / 4; i += NT) dst[i] = src[i];
}

extern "C" void kernel_launch(void* const* d_in, const int* in_sizes, int n_in,
                              void* d_out, int out_size) {
    const int* idx = (const int*)d_in[0];
    const float* tok_emb = (const float*)d_in[1];
    const float* pos_enc = (const float*)d_in[2];
    const float* q_w = (const float*)d_in[3];
    const float* k_w = (const float*)d_in[4];
    const float* v_w = (const float*)d_in[5];
    const float* out_w = (const float*)d_in[6];
    const float* ln1_g = (const float*)d_in[7];
    const float* ln1_b = (const float*)d_in[8];
    const float* ln2_g = (const float*)d_in[9];
    const float* ln2_b = (const float*)d_in[10];
    const float* lnf_g = (const float*)d_in[11];
    const float* lnf_b = (const float*)d_in[12];
    const float* ffn_w1 = (const float*)d_in[13];
    const float* ffn_b1 = (const float*)d_in[14];
    const float* ffn_w2 = (const float*)d_in[15];
    const float* ffn_b2 = (const float*)d_in[16];
    const float* head_w = (const float*)d_in[17];
    float* out = (float*)d_out;

    prep_kernel<<<1, 1024>>>(tok_emb, pos_enc, q_w, k_w, v_w, out_w,
                             ln1_g, ln1_b, ln2_g, ln2_b, lnf_g, lnf_b,
                             ffn_w1, ffn_b1, ffn_w2, ffn_b2, head_w);

    void* scratch_ptr = nullptr;
    cudaGetSymbolAddress(&scratch_ptr, g_scratch);
    cudaMemcpyToSymbolAsync(c_pack, scratch_ptr, NPK * sizeof(float2), 0,
                            cudaMemcpyDeviceToDevice, 0);

    const int B = in_sizes[0] / T_SEQ;   // 65536
    dim3 block(RWS, TH);
    dim3 grid(B / RWS);
    add_tf_kernel<<<grid, block>>>(idx, tok_emb, pos_enc, out);
}

// round 12
// speedup vs baseline: 1.0277x; 1.0277x over previous
#include <cuda_runtime.h>

typedef unsigned long long u64;

#define T_SEQ 34
#define RWS 16          // rows per block
#define TH 17           // paired positions: thread t handles t and 33-t
#define NT (RWS * TH)   // 272 threads
#define VCB 14

// ---- constant-packed weights (float2) ----
//  0 M(9): head-paired fused score matrix, scaled by rs3*log2e
//  54 N(36,dup): fused outw·vw | 90 w1(18,dup) | 108 w2(18,dup)
//  126 b1(3) | 129 b2(6) | 135 l1g 141 l1b 147 l2g 153 l2b 159 lfg 165 lfb
//  171 wlog(84,dup)   -> total 255
#define NPK 255
__constant__ __align__(8) float2 c_pack[NPK];
__device__ __align__(8) float2 g_scratch[NPK];

__device__ __forceinline__ u64 pk2(float lo, float hi) {
    u64 r; asm("mov.b64 %0, {%1, %2};" : "=l"(r) : "f"(lo), "f"(hi)); return r;
}
__device__ __forceinline__ void up2(u64 v, float& a, float& b) {
    asm("mov.b64 {%0, %1}, %2;" : "=f"(a), "=f"(b) : "l"(v));
}
__device__ __forceinline__ u64 f2fma(u64 a, u64 b, u64 c) {
    u64 d; asm("fma.rn.f32x2 %0, %1, %2, %3;" : "=l"(d) : "l"(a), "l"(b), "l"(c)); return d;
}
__device__ __forceinline__ u64 f2add(u64 a, u64 b) {
    u64 d; asm("add.rn.f32x2 %0, %1, %2;" : "=l"(d) : "l"(a), "l"(b)); return d;
}
__device__ __forceinline__ u64 f2mul(u64 a, u64 b) {
    u64 d; asm("mul.rn.f32x2 %0, %1, %2;" : "=l"(d) : "l"(a), "l"(b)); return d;
}
__device__ __forceinline__ float ex2(float x) {
    float y; asm("ex2.approx.f32 %0, %1;" : "=f"(y) : "f"(x)); return y;
}
__device__ __forceinline__ u64 cw(int i) {
    return *reinterpret_cast<const u64*>(&c_pack[i]);
}

// packed LayerNorm over 6 dims; lanes = two independent tokens
__device__ __forceinline__ void ln6p(const u64* x, int gi, int bi, u64* o) {
    u64 s = f2add(f2add(f2add(x[0], x[1]), f2add(x[2], x[3])), f2add(x[4], x[5]));
    u64 negmu = f2mul(s, pk2(-1.0f / 6.0f, -1.0f / 6.0f));
    u64 d0 = f2add(x[0], negmu), d1 = f2add(x[1], negmu), d2 = f2add(x[2], negmu);
    u64 d3 = f2add(x[3], negmu), d4 = f2add(x[4], negmu), d5 = f2add(x[5], negmu);
    u64 v = f2mul(d0, d0);
    v = f2fma(d1, d1, v); v = f2fma(d2, d2, v);
    v = f2fma(d3, d3, v); v = f2fma(d4, d4, v); v = f2fma(d5, d5, v);
    float va, vb; up2(v, va, vb);
    float ia = rsqrtf(va * (1.0f / 6.0f) + 1e-5f);
    float ib = rsqrtf(vb * (1.0f / 6.0f) + 1e-5f);
    u64 inv = pk2(ia, ib);
    o[0] = f2fma(f2mul(d0, inv), cw(gi + 0), cw(bi + 0));
    o[1] = f2fma(f2mul(d1, inv), cw(gi + 1), cw(bi + 1));
    o[2] = f2fma(f2mul(d2, inv), cw(gi + 2), cw(bi + 2));
    o[3] = f2fma(f2mul(d3, inv), cw(gi + 3), cw(bi + 3));
    o[4] = f2fma(f2mul(d4, inv), cw(gi + 4), cw(bi + 4));
    o[5] = f2fma(f2mul(d5, inv), cw(gi + 5), cw(bi + 5));
}

__global__ void prep_kernel(
    const float* __restrict__ tok_emb,
    const float* __restrict__ qw, const float* __restrict__ kw, const float* __restrict__ vw,
    const float* __restrict__ outw,
    const float* __restrict__ ln1g, const float* __restrict__ ln1b,
    const float* __restrict__ ln2g, const float* __restrict__ ln2b,
    const float* __restrict__ lnfg, const float* __restrict__ lnfb,
    const float* __restrict__ fw1, const float* __restrict__ fb1,
    const float* __restrict__ fw2, const float* __restrict__ fb2,
    const float* __restrict__ headw)
{
    int i = threadIdx.x;
    if (i >= NPK) return;
    const float qscale = 0.57735026918962576f * 1.4426950408889634f;  // rs3 * log2(e)
    float lo = 0.f, hi = 0.f;
    if (i < 9) {                    // M_h[d][c] = sum_o qw[h][o][d]*kw[h][o][c] * qscale
        int d = i / 3, c = i % 3;
        float m0 = 0.f, m1 = 0.f;
        for (int o = 0; o < 3; o++) {
            m0 += qw[(0 + o) * 3 + d] * kw[(0 + o) * 3 + c];
            m1 += qw[(3 + o) * 3 + d] * kw[(3 + o) * 3 + c];
        }
        lo = m0 * qscale; hi = m1 * qscale;
    }
    else if (i >= 54 && i < 90) {   // N[d][o=h*3+c] = sum_k outw[d][h3+k]*vw[h3+k][c]
        int d = (i - 54) / 6, o = (i - 54) % 6;
        int h = o / 3, c = o % 3;
        float n = 0.f;
        for (int k = 0; k < 3; k++)
            n += outw[d * 6 + h * 3 + k] * vw[(h * 3 + k) * 3 + c];
        lo = n; hi = n;
    }
    else if (i >= 90 && i < 108)  { lo = fw1[i - 90]; hi = lo; }
    else if (i >= 108 && i < 126) { lo = fw2[i - 108]; hi = lo; }
    else if (i >= 126 && i < 129) { lo = fb1[i - 126]; hi = lo; }
    else if (i >= 129 && i < 135) { lo = fb2[i - 129]; hi = lo; }
    else if (i >= 135 && i < 141) { lo = ln1g[i - 135]; hi = lo; }
    else if (i >= 141 && i < 147) { lo = ln1b[i - 141]; hi = lo; }
    else if (i >= 147 && i < 153) { lo = ln2g[i - 147]; hi = lo; }
    else if (i >= 153 && i < 159) { lo = ln2b[i - 153]; hi = lo; }
    else if (i >= 159 && i < 165) { lo = lnfg[i - 159]; hi = lo; }
    else if (i >= 165 && i < 171) { lo = lnfb[i - 165]; hi = lo; }
    else if (i >= 171) {
        int v = (i - 171) / 6, d = (i - 171) % 6;
        lo = tok_emb[v * 3 + 0] * headw[0 * 6 + d]
           + tok_emb[v * 3 + 1] * headw[1 * 6 + d]
           + tok_emb[v * 3 + 2] * headw[2 * 6 + d];
        hi = lo;
    }
    g_scratch[i] = make_float2(lo, hi);
}

__global__ __launch_bounds__(NT, 5) void add_tf_kernel(
    const int* __restrict__ idx,
    const float* __restrict__ tok_emb, const float* __restrict__ pos_enc,
    float* __restrict__ out)
{
    __shared__ float s_te[42], s_pe[102];
    __shared__ int s_idx[RWS * T_SEQ];
    // attention buffer: per j, 6 DUPLICATED u64: (h0,h0)(h1,h1)(h2,h2)(x0,x0)(x1,x1)(x2,x2)
    // row stride 105 float4 = 420 words == 4 (mod 32) -> conflict-free LDS.128
    __shared__ union {
        float4 hd[RWS][105];
        float ob[RWS * T_SEQ * VCB];   // 7616 floats
    } uni;

    const int r = threadIdx.x;      // row in block (0..15)
    const int t = threadIdx.y;      // pair index (0..16)
    const int tid = t * RWS + r;

    for (int i = tid; i < 42; i += NT) s_te[i] = tok_emb[i];
    for (int i = tid; i < 102; i += NT) s_pe[i] = pos_enc[i];
    {
        const int4* gsrc = (const int4*)(idx + (size_t)blockIdx.x * (RWS * T_SEQ));
        int4* sdst = (int4*)s_idx;
        for (int i = tid; i < (RWS * T_SEQ) / 4; i += NT) sdst[i] = gsrc[i];
    }
    __syncthreads();

    const int tA = t, tB = 33 - t;
    const int tokA = s_idx[r * T_SEQ + tA];
    const int tokB = s_idx[r * T_SEQ + tB];

    u64 uA0, uA1, uA2, uB0, uB1, uB2;   // u_h = M_h^T h_pos, head-packed per token
    {
        u64 x2[6];
        x2[0] = pk2(s_te[tokA * 3 + 0], s_te[tokB * 3 + 0]);
        x2[1] = pk2(s_te[tokA * 3 + 1], s_te[tokB * 3 + 1]);
        x2[2] = pk2(s_te[tokA * 3 + 2], s_te[tokB * 3 + 2]);
        x2[3] = pk2(s_pe[tA * 3 + 0], s_pe[tB * 3 + 0]);
        x2[4] = pk2(s_pe[tA * 3 + 1], s_pe[tB * 3 + 1]);
        x2[5] = pk2(s_pe[tA * 3 + 2], s_pe[tB * 3 + 2]);

        u64 h1[6];
        ln6p(x2, 135, 141, h1);

        float hA0, hB0, hA1, hB1, hA2, hB2;   // pos part
        up2(h1[3], hA0, hB0); up2(h1[4], hA1, hB1); up2(h1[5], hA2, hB2);
        float xA0, xB0, xA1, xB1, xA2, xB2;   // tok part
        up2(h1[0], xA0, xB0); up2(h1[1], xA1, xB1); up2(h1[2], xA2, xB2);

        // stage DUPLICATED h_pos + x_tok (48B per position, 3 STS.128)
        float4* pA = &uni.hd[r][tA * 3];
        pA[0] = make_float4(hA0, hA0, hA1, hA1);
        pA[1] = make_float4(hA2, hA2, xA0, xA0);
        pA[2] = make_float4(xA1, xA1, xA2, xA2);
        float4* pB = &uni.hd[r][tB * 3];
        pB[0] = make_float4(hB0, hB0, hB1, hB1);
        pB[1] = make_float4(hB2, hB2, xB0, xB0);
        pB[2] = make_float4(xB1, xB1, xB2, xB2);

        // u_h[c] = sum_d h[d] * M_h[d][c], head-packed
        u64 hdA0 = pk2(hA0, hA0), hdA1 = pk2(hA1, hA1), hdA2 = pk2(hA2, hA2);
        u64 hdB0 = pk2(hB0, hB0), hdB1 = pk2(hB1, hB1), hdB2 = pk2(hB2, hB2);
        uA0 = f2fma(hdA2, cw(6), f2fma(hdA1, cw(3), f2mul(hdA0, cw(0))));
        uA1 = f2fma(hdA2, cw(7), f2fma(hdA1, cw(4), f2mul(hdA0, cw(1))));
        uA2 = f2fma(hdA2, cw(8), f2fma(hdA1, cw(5), f2mul(hdA0, cw(2))));
        uB0 = f2fma(hdB2, cw(6), f2fma(hdB1, cw(3), f2mul(hdB0, cw(0))));
        uB1 = f2fma(hdB2, cw(7), f2fma(hdB1, cw(4), f2mul(hdB0, cw(1))));
        uB2 = f2fma(hdB2, cw(8), f2fma(hdB1, cw(5), f2mul(hdB0, cw(2))));
    }
    __syncthreads();

    // ---- causal attention: duplicated operands land as aligned reg pairs (no movs) ----
    u64 ssA = 0ULL, aA0 = 0ULL, aA1 = 0ULL, aA2 = 0ULL;
    u64 ssB = 0ULL, aB0 = 0ULL, aB1 = 0ULL, aB2 = 0ULL;
    const ulonglong2* pr = (const ulonglong2*)&uni.hd[r][0];
#pragma unroll 2
    for (int j = 0; j <= t; j++) {
        ulonglong2 q0 = pr[j * 3], q1 = pr[j * 3 + 1], q2 = pr[j * 3 + 2];
        u64 hh0 = q0.x, hh1 = q0.y, hh2 = q1.x;
        u64 xx0 = q1.y, xx1 = q2.x, xx2 = q2.y;

        u64 sB = f2fma(uB2, hh2, f2fma(uB1, hh1, f2mul(uB0, hh0)));
        float sb0, sb1; up2(sB, sb0, sb1);
        u64 eB = pk2(ex2(sb0), ex2(sb1));
        ssB = f2add(ssB, eB);
        aB0 = f2fma(eB, xx0, aB0); aB1 = f2fma(eB, xx1, aB1); aB2 = f2fma(eB, xx2, aB2);

        u64 sA = f2fma(uA2, hh2, f2fma(uA1, hh1, f2mul(uA0, hh0)));
        float sa0, sa1; up2(sA, sa0, sa1);
        u64 eA = pk2(ex2(sa0), ex2(sa1));
        ssA = f2add(ssA, eA);
        aA0 = f2fma(eA, xx0, aA0); aA1 = f2fma(eA, xx1, aA1); aA2 = f2fma(eA, xx2, aA2);
    }
#pragma unroll 2
    for (int j = t + 1; j <= tB; j++) {
        ulonglong2 q0 = pr[j * 3], q1 = pr[j * 3 + 1], q2 = pr[j * 3 + 2];
        u64 hh0 = q0.x, hh1 = q0.y, hh2 = q1.x;
        u64 xx0 = q1.y, xx1 = q2.x, xx2 = q2.y;

        u64 sB = f2fma(uB2, hh2, f2fma(uB1, hh1, f2mul(uB0, hh0)));
        float sb0, sb1; up2(sB, sb0, sb1);
        u64 eB = pk2(ex2(sb0), ex2(sb1));
        ssB = f2add(ssB, eB);
        aB0 = f2fma(eB, xx0, aB0); aB1 = f2fma(eB, xx1, aB1); aB2 = f2fma(eB, xx2, aB2);
    }
    __syncthreads();   // hd -> ob buffer reuse

    // normalize head-packed x-sums -> token-packed o2 (W_v folded into N)
    u64 o2[6];
    {
        float s0, s1; up2(ssA, s0, s1);
        u64 invA = pk2(__fdividef(1.0f, s0), __fdividef(1.0f, s1));
        up2(ssB, s0, s1);
        u64 invB = pk2(__fdividef(1.0f, s0), __fdividef(1.0f, s1));
        aA0 = f2mul(aA0, invA); aA1 = f2mul(aA1, invA); aA2 = f2mul(aA2, invA);
        aB0 = f2mul(aB0, invB); aB1 = f2mul(aB1, invB); aB2 = f2mul(aB2, invB);

        float oA[6], oB[6];
        up2(aA0, oA[0], oA[3]); up2(aA1, oA[1], oA[4]); up2(aA2, oA[2], oA[5]);
        up2(aB0, oB[0], oB[3]); up2(aB1, oB[1], oB[4]); up2(aB2, oB[2], oB[5]);
#pragma unroll
        for (int o = 0; o < 6; o++) o2[o] = pk2(oA[o], oB[o]);
    }

    // rebuild x2 (cheap; kept regs low through the loop)
    u64 xa[6];
    xa[0] = pk2(s_te[tokA * 3 + 0], s_te[tokB * 3 + 0]);
    xa[1] = pk2(s_te[tokA * 3 + 1], s_te[tokB * 3 + 1]);
    xa[2] = pk2(s_te[tokA * 3 + 2], s_te[tokB * 3 + 2]);
    xa[3] = pk2(s_pe[tA * 3 + 0], s_pe[tB * 3 + 0]);
    xa[4] = pk2(s_pe[tA * 3 + 1], s_pe[tB * 3 + 1]);
    xa[5] = pk2(s_pe[tA * 3 + 2], s_pe[tB * 3 + 2]);

    // fused (outw·vw) projection + residual
#pragma unroll
    for (int d = 0; d < 6; d++) {
        u64 a = xa[d];
#pragma unroll
        for (int o = 0; o < 6; o++) a = f2fma(o2[o], cw(54 + d * 6 + o), a);
        xa[d] = a;
    }

    // FFN (exact GELU) + residual
    {
        u64 h2[6];
        ln6p(xa, 147, 153, h2);
        u64 g2[3];
#pragma unroll
        for (int f = 0; f < 3; f++) {
            u64 u = cw(126 + f);
#pragma unroll
            for (int d = 0; d < 6; d++) u = f2fma(h2[d], cw(90 + f * 6 + d), u);
            float ua, ub; up2(u, ua, ub);
            float ga = 0.5f * ua * (1.0f + erff(ua * 0.70710678118654752f));
            float gb = 0.5f * ub * (1.0f + erff(ub * 0.70710678118654752f));
            g2[f] = pk2(ga, gb);
        }
#pragma unroll
        for (int d = 0; d < 6; d++) {
            u64 y = cw(129 + d);
#pragma unroll
            for (int f = 0; f < 3; f++) y = f2fma(g2[f], cw(108 + d * 3 + f), y);
            xa[d] = f2add(xa[d], y);
        }
    }

    // final LN + fused logits -> smem staging (float2 stores)
    u64 xf[6];
    ln6p(xa, 159, 165, xf);

    float2* soA = (float2*)&uni.ob[(r * T_SEQ + tA) * VCB];
    float2* soB = (float2*)&uni.ob[(r * T_SEQ + tB) * VCB];
#pragma unroll
    for (int v = 0; v < VCB; v += 2) {
        u64 acc0 = f2mul(xf[0], cw(171 + v * 6 + 0));
        u64 acc1 = f2mul(xf[0], cw(171 + (v + 1) * 6 + 0));
#pragma unroll
        for (int d = 1; d < 6; d++) {
            acc0 = f2fma(xf[d], cw(171 + v * 6 + d), acc0);
            acc1 = f2fma(xf[d], cw(171 + (v + 1) * 6 + d), acc1);
        }
        float a0, b0, a1, b1;
        up2(acc0, a0, b0); up2(acc1, a1, b1);
        soA[v / 2] = make_float2(a0, a1);
        soB[v / 2] = make_float2(b0, b1);
    }
    __syncthreads();

    // coalesced block-contiguous output write
    float4* dst = (float4*)(out + (size_t)blockIdx.x * (RWS * T_SEQ * VCB));
    const float4* src = (const float4*)uni.ob;
#pragma unroll
    for (int i = tid; i < (RWS * T_SEQ * VCB) / 4; i += NT) dst[i] = src[i];
}

extern "C" void kernel_launch(void* const* d_in, const int* in_sizes, int n_in,
                              void* d_out, int out_size) {
    const int* idx = (const int*)d_in[0];
    const float* tok_emb = (const float*)d_in[1];
    const float* pos_enc = (const float*)d_in[2];
    const float* q_w = (const float*)d_in[3];
    const float* k_w = (const float*)d_in[4];
    const float* v_w = (const float*)d_in[5];
    const float* out_w = (const float*)d_in[6];
    const float* ln1_g = (const float*)d_in[7];
    const float* ln1_b = (const float*)d_in[8];
    const float* ln2_g = (const float*)d_in[9];
    const float* ln2_b = (const float*)d_in[10];
    const float* lnf_g = (const float*)d_in[11];
    const float* lnf_b = (const float*)d_in[12];
    const float* ffn_w1 = (const float*)d_in[13];
    const float* ffn_b1 = (const float*)d_in[14];
    const float* ffn_w2 = (const float*)d_in[15];
    const float* ffn_b2 = (const float*)d_in[16];
    const float* head_w = (const float*)d_in[17];
    float* out = (float*)d_out;

    prep_kernel<<<1, 256>>>(tok_emb, q_w, k_w, v_w, out_w,
                            ln1_g, ln1_b, ln2_g, ln2_b, lnf_g, lnf_b,
                            ffn_w1, ffn_b1, ffn_w2, ffn_b2, head_w);

    void* scratch_ptr = nullptr;
    cudaGetSymbolAddress(&scratch_ptr, g_scratch);
    cudaMemcpyToSymbolAsync(c_pack, scratch_ptr, NPK * sizeof(float2), 0,
                            cudaMemcpyDeviceToDevice, 0);

    const int B = in_sizes[0] / T_SEQ;   // 65536
    dim3 block(RWS, TH);
    dim3 grid(B / RWS);
    add_tf_kernel<<<grid, block>>>(idx, tok_emb, pos_enc, out);
}

// round 13
// speedup vs baseline: 1.2581x; 1.2242x over previous
#include <cuda_runtime.h>

typedef unsigned long long u64;

#define T_SEQ 34
#define RWS 16          // rows per block
#define TH 17           // paired positions: thread t handles t and 33-t
#define NT (RWS * TH)   // 272 threads
#define VCB 14

// ---- constant-packed weights (float2) ----
//  0 M(9): head-paired fused score matrix, scaled by rs3*log2e
//  9 hw(18,dup): head_w[c][d]   | 27 te(42,dup): tok_emb[v][c]
//  69 N(36,dup): fused outw·vw  | 105 w1(18,dup) | 123 w2(18,dup)
//  141 b1(3) | 144 b2(6)
//  150 l1g 156 l1b 162 l2g 168 l2b 174 lfg 180 lfb  -> total 186
#define NPK 186
__constant__ __align__(8) float2 c_pack[NPK];
__device__ __align__(8) float2 g_scratch[NPK];

__device__ __forceinline__ u64 pk2(float lo, float hi) {
    u64 r; asm("mov.b64 %0, {%1, %2};" : "=l"(r) : "f"(lo), "f"(hi)); return r;
}
__device__ __forceinline__ void up2(u64 v, float& a, float& b) {
    asm("mov.b64 {%0, %1}, %2;" : "=f"(a), "=f"(b) : "l"(v));
}
__device__ __forceinline__ u64 f2fma(u64 a, u64 b, u64 c) {
    u64 d; asm("fma.rn.f32x2 %0, %1, %2, %3;" : "=l"(d) : "l"(a), "l"(b), "l"(c)); return d;
}
__device__ __forceinline__ u64 f2add(u64 a, u64 b) {
    u64 d; asm("add.rn.f32x2 %0, %1, %2;" : "=l"(d) : "l"(a), "l"(b)); return d;
}
__device__ __forceinline__ u64 f2mul(u64 a, u64 b) {
    u64 d; asm("mul.rn.f32x2 %0, %1, %2;" : "=l"(d) : "l"(a), "l"(b)); return d;
}
__device__ __forceinline__ float ex2(float x) {
    float y; asm("ex2.approx.f32 %0, %1;" : "=f"(y) : "f"(x)); return y;
}
__device__ __forceinline__ u64 cw(int i) {
    return *reinterpret_cast<const u64*>(&c_pack[i]);
}

// packed LayerNorm over 6 dims; lanes = two independent tokens
__device__ __forceinline__ void ln6p(const u64* x, int gi, int bi, u64* o) {
    u64 s = f2add(f2add(f2add(x[0], x[1]), f2add(x[2], x[3])), f2add(x[4], x[5]));
    u64 negmu = f2mul(s, pk2(-1.0f / 6.0f, -1.0f / 6.0f));
    u64 d0 = f2add(x[0], negmu), d1 = f2add(x[1], negmu), d2 = f2add(x[2], negmu);
    u64 d3 = f2add(x[3], negmu), d4 = f2add(x[4], negmu), d5 = f2add(x[5], negmu);
    u64 v = f2mul(d0, d0);
    v = f2fma(d1, d1, v); v = f2fma(d2, d2, v);
    v = f2fma(d3, d3, v); v = f2fma(d4, d4, v); v = f2fma(d5, d5, v);
    float va, vb; up2(v, va, vb);
    float ia = rsqrtf(va * (1.0f / 6.0f) + 1e-5f);
    float ib = rsqrtf(vb * (1.0f / 6.0f) + 1e-5f);
    u64 inv = pk2(ia, ib);
    o[0] = f2fma(f2mul(d0, inv), cw(gi + 0), cw(bi + 0));
    o[1] = f2fma(f2mul(d1, inv), cw(gi + 1), cw(bi + 1));
    o[2] = f2fma(f2mul(d2, inv), cw(gi + 2), cw(bi + 2));
    o[3] = f2fma(f2mul(d3, inv), cw(gi + 3), cw(bi + 3));
    o[4] = f2fma(f2mul(d4, inv), cw(gi + 4), cw(bi + 4));
    o[5] = f2fma(f2mul(d5, inv), cw(gi + 5), cw(bi + 5));
}

__global__ void prep_kernel(
    const float* __restrict__ tok_emb,
    const float* __restrict__ qw, const float* __restrict__ kw, const float* __restrict__ vw,
    const float* __restrict__ outw,
    const float* __restrict__ ln1g, const float* __restrict__ ln1b,
    const float* __restrict__ ln2g, const float* __restrict__ ln2b,
    const float* __restrict__ lnfg, const float* __restrict__ lnfb,
    const float* __restrict__ fw1, const float* __restrict__ fb1,
    const float* __restrict__ fw2, const float* __restrict__ fb2,
    const float* __restrict__ headw)
{
    int i = threadIdx.x;
    if (i >= NPK) return;
    const float qscale = 0.57735026918962576f * 1.4426950408889634f;  // rs3 * log2(e)
    float lo = 0.f, hi = 0.f;
    if (i < 9) {                    // M_h[d][c] = sum_o qw[h][o][d]*kw[h][o][c] * qscale
        int d = i / 3, c = i % 3;
        float m0 = 0.f, m1 = 0.f;
        for (int o = 0; o < 3; o++) {
            m0 += qw[(0 + o) * 3 + d] * kw[(0 + o) * 3 + c];
            m1 += qw[(3 + o) * 3 + d] * kw[(3 + o) * 3 + c];
        }
        lo = m0 * qscale; hi = m1 * qscale;
    }
    else if (i < 27)  { lo = headw[i - 9]; hi = lo; }       // head_w[c][d]
    else if (i < 69)  { lo = tok_emb[i - 27]; hi = lo; }    // te[v][c]
    else if (i < 105) {   // N[d][o=h*3+c] = sum_k outw[d][h3+k]*vw[h3+k][c]
        int d = (i - 69) / 6, o = (i - 69) % 6;
        int h = o / 3, c = o % 3;
        float n = 0.f;
        for (int k = 0; k < 3; k++)
            n += outw[d * 6 + h * 3 + k] * vw[(h * 3 + k) * 3 + c];
        lo = n; hi = n;
    }
    else if (i < 123) { lo = fw1[i - 105]; hi = lo; }
    else if (i < 141) { lo = fw2[i - 123]; hi = lo; }
    else if (i < 144) { lo = fb1[i - 141]; hi = lo; }
    else if (i < 150) { lo = fb2[i - 144]; hi = lo; }
    else if (i < 156) { lo = ln1g[i - 150]; hi = lo; }
    else if (i < 162) { lo = ln1b[i - 156]; hi = lo; }
    else if (i < 168) { lo = ln2g[i - 162]; hi = lo; }
    else if (i < 174) { lo = ln2b[i - 168]; hi = lo; }
    else if (i < 180) { lo = lnfg[i - 174]; hi = lo; }
    else              { lo = lnfb[i - 180]; hi = lo; }
    g_scratch[i] = make_float2(lo, hi);
}

__global__ __launch_bounds__(NT, 5) void add_tf_kernel(
    const int* __restrict__ idx,
    const float* __restrict__ tok_emb, const float* __restrict__ pos_enc,
    float* __restrict__ out)
{
    __shared__ float s_te[42], s_pe[102];
    __shared__ int s_idx[RWS * T_SEQ];
    // attention buffers and output staging live in disjoint phases -> union
    __shared__ union {
        struct {
            float4 hk[RWS][35];   // (h0,h1,h2,x0) per j
            float2 hx[RWS][35];   // (x1,x2) per j
        } att;
        float ob[RWS * T_SEQ * VCB];   // 7616 floats
    } uni;

    const int r = threadIdx.x;      // row in block (0..15)
    const int t = threadIdx.y;      // pair index (0..16)
    const int tid = t * RWS + r;

    for (int i = tid; i < 42; i += NT) s_te[i] = tok_emb[i];
    for (int i = tid; i < 102; i += NT) s_pe[i] = pos_enc[i];
    {
        const int4* gsrc = (const int4*)(idx + (size_t)blockIdx.x * (RWS * T_SEQ));
        int4* sdst = (int4*)s_idx;
        for (int i = tid; i < (RWS * T_SEQ) / 4; i += NT) sdst[i] = gsrc[i];
    }
    __syncthreads();

    const int tA = t, tB = 33 - t;
    const int tokA = s_idx[r * T_SEQ + tA];
    const int tokB = s_idx[r * T_SEQ + tB];

    u64 uA0, uA1, uA2, uB0, uB1, uB2;   // u_h = M_h^T h_pos, head-packed per token
    {
        u64 x2[6];
        x2[0] = pk2(s_te[tokA * 3 + 0], s_te[tokB * 3 + 0]);
        x2[1] = pk2(s_te[tokA * 3 + 1], s_te[tokB * 3 + 1]);
        x2[2] = pk2(s_te[tokA * 3 + 2], s_te[tokB * 3 + 2]);
        x2[3] = pk2(s_pe[tA * 3 + 0], s_pe[tB * 3 + 0]);
        x2[4] = pk2(s_pe[tA * 3 + 1], s_pe[tB * 3 + 1]);
        x2[5] = pk2(s_pe[tA * 3 + 2], s_pe[tB * 3 + 2]);

        u64 h1[6];
        ln6p(x2, 150, 156, h1);

        float hA0, hB0, hA1, hB1, hA2, hB2;   // pos part
        up2(h1[3], hA0, hB0); up2(h1[4], hA1, hB1); up2(h1[5], hA2, hB2);
        float xA0, xB0, xA1, xB1, xA2, xB2;   // tok part
        up2(h1[0], xA0, xB0); up2(h1[1], xA1, xB1); up2(h1[2], xA2, xB2);

        // stage raw h_pos + x_tok (24B per position)
        uni.att.hk[r][tA] = make_float4(hA0, hA1, hA2, xA0);
        uni.att.hx[r][tA] = make_float2(xA1, xA2);
        uni.att.hk[r][tB] = make_float4(hB0, hB1, hB2, xB0);
        uni.att.hx[r][tB] = make_float2(xB1, xB2);

        // u_h[c] = sum_d h[d] * M_h[d][c], head-packed
        u64 hdA0 = pk2(hA0, hA0), hdA1 = pk2(hA1, hA1), hdA2 = pk2(hA2, hA2);
        u64 hdB0 = pk2(hB0, hB0), hdB1 = pk2(hB1, hB1), hdB2 = pk2(hB2, hB2);
        uA0 = f2fma(hdA2, cw(6), f2fma(hdA1, cw(3), f2mul(hdA0, cw(0))));
        uA1 = f2fma(hdA2, cw(7), f2fma(hdA1, cw(4), f2mul(hdA0, cw(1))));
        uA2 = f2fma(hdA2, cw(8), f2fma(hdA1, cw(5), f2mul(hdA0, cw(2))));
        uB0 = f2fma(hdB2, cw(6), f2fma(hdB1, cw(3), f2mul(hdB0, cw(0))));
        uB1 = f2fma(hdB2, cw(7), f2fma(hdB1, cw(4), f2mul(hdB0, cw(1))));
        uB2 = f2fma(hdB2, cw(8), f2fma(hdB1, cw(5), f2mul(hdB0, cw(2))));
    }
    __syncthreads();

    // ---- causal attention: s_h = u_h . h_j ; accumulate sum(e), sum(e * x_tok) ----
    u64 ssA = 0ULL, aA0 = 0ULL, aA1 = 0ULL, aA2 = 0ULL;
    u64 ssB = 0ULL, aB0 = 0ULL, aB1 = 0ULL, aB2 = 0ULL;
    const float4* ph = uni.att.hk[r];
    const float2* px = uni.att.hx[r];
#pragma unroll 2
    for (int j = 0; j <= t; j++) {
        float4 H = ph[j]; float2 X = px[j];
        u64 hh0 = pk2(H.x, H.x), hh1 = pk2(H.y, H.y), hh2 = pk2(H.z, H.z);
        u64 xx0 = pk2(H.w, H.w), xx1 = pk2(X.x, X.x), xx2 = pk2(X.y, X.y);

        u64 sB = f2fma(uB2, hh2, f2fma(uB1, hh1, f2mul(uB0, hh0)));
        float sb0, sb1; up2(sB, sb0, sb1);
        u64 eB = pk2(ex2(sb0), ex2(sb1));
        ssB = f2add(ssB, eB);
        aB0 = f2fma(eB, xx0, aB0); aB1 = f2fma(eB, xx1, aB1); aB2 = f2fma(eB, xx2, aB2);

        u64 sA = f2fma(uA2, hh2, f2fma(uA1, hh1, f2mul(uA0, hh0)));
        float sa0, sa1; up2(sA, sa0, sa1);
        u64 eA = pk2(ex2(sa0), ex2(sa1));
        ssA = f2add(ssA, eA);
        aA0 = f2fma(eA, xx0, aA0); aA1 = f2fma(eA, xx1, aA1); aA2 = f2fma(eA, xx2, aA2);
    }
#pragma unroll 2
    for (int j = t + 1; j <= tB; j++) {
        float4 H = ph[j]; float2 X = px[j];
        u64 hh0 = pk2(H.x, H.x), hh1 = pk2(H.y, H.y), hh2 = pk2(H.z, H.z);
        u64 xx0 = pk2(H.w, H.w), xx1 = pk2(X.x, X.x), xx2 = pk2(X.y, X.y);

        u64 sB = f2fma(uB2, hh2, f2fma(uB1, hh1, f2mul(uB0, hh0)));
        float sb0, sb1; up2(sB, sb0, sb1);
        u64 eB = pk2(ex2(sb0), ex2(sb1));
        ssB = f2add(ssB, eB);
        aB0 = f2fma(eB, xx0, aB0); aB1 = f2fma(eB, xx1, aB1); aB2 = f2fma(eB, xx2, aB2);
    }
    __syncthreads();   // att -> ob buffer reuse

    // normalize head-packed x-sums -> token-packed o2 (W_v folded into N)
    u64 o2[6];
    {
        float s0, s1; up2(ssA, s0, s1);
        u64 invA = pk2(__fdividef(1.0f, s0), __fdividef(1.0f, s1));
        up2(ssB, s0, s1);
        u64 invB = pk2(__fdividef(1.0f, s0), __fdividef(1.0f, s1));
        aA0 = f2mul(aA0, invA); aA1 = f2mul(aA1, invA); aA2 = f2mul(aA2, invA);
        aB0 = f2mul(aB0, invB); aB1 = f2mul(aB1, invB); aB2 = f2mul(aB2, invB);

        float oA[6], oB[6];
        up2(aA0, oA[0], oA[3]); up2(aA1, oA[1], oA[4]); up2(aA2, oA[2], oA[5]);
        up2(aB0, oB[0], oB[3]); up2(aB1, oB[1], oB[4]); up2(aB2, oB[2], oB[5]);
#pragma unroll
        for (int o = 0; o < 6; o++) o2[o] = pk2(oA[o], oB[o]);
    }

    // rebuild x2 (cheap; kept regs low through the loop)
    u64 xa[6];
    xa[0] = pk2(s_te[tokA * 3 + 0], s_te[tokB * 3 + 0]);
    xa[1] = pk2(s_te[tokA * 3 + 1], s_te[tokB * 3 + 1]);
    xa[2] = pk2(s_te[tokA * 3 + 2], s_te[tokB * 3 + 2]);
    xa[3] = pk2(s_pe[tA * 3 + 0], s_pe[tB * 3 + 0]);
    xa[4] = pk2(s_pe[tA * 3 + 1], s_pe[tB * 3 + 1]);
    xa[5] = pk2(s_pe[tA * 3 + 2], s_pe[tB * 3 + 2]);

    // fused (outw·vw) projection + residual
#pragma unroll
    for (int d = 0; d < 6; d++) {
        u64 a = xa[d];
#pragma unroll
        for (int o = 0; o < 6; o++) a = f2fma(o2[o], cw(69 + d * 6 + o), a);
        xa[d] = a;
    }

    // FFN (exact GELU) + residual
    {
        u64 h2[6];
        ln6p(xa, 162, 168, h2);
        u64 g2[3];
#pragma unroll
        for (int f = 0; f < 3; f++) {
            u64 u = cw(141 + f);
#pragma unroll
            for (int d = 0; d < 6; d++) u = f2fma(h2[d], cw(105 + f * 6 + d), u);
            float ua, ub; up2(u, ua, ub);
            float ga = 0.5f * ua * (1.0f + erff(ua * 0.70710678118654752f));
            float gb = 0.5f * ub * (1.0f + erff(ub * 0.70710678118654752f));
            g2[f] = pk2(ga, gb);
        }
#pragma unroll
        for (int d = 0; d < 6; d++) {
            u64 y = cw(144 + d);
#pragma unroll
            for (int f = 0; f < 3; f++) y = f2fma(g2[f], cw(123 + d * 3 + f), y);
            xa[d] = f2add(xa[d], y);
        }
    }

    // final LN + rank-3 logits -> smem staging
    u64 xf[6];
    ln6p(xa, 174, 180, xf);

    // z[c] = sum_d xf[d] * head_w[c][d]  (3 packed values)
    u64 z[3];
#pragma unroll
    for (int c = 0; c < 3; c++) {
        u64 acc = f2mul(xf[0], cw(9 + c * 6 + 0));
#pragma unroll
        for (int d = 1; d < 6; d++) acc = f2fma(xf[d], cw(9 + c * 6 + d), acc);
        z[c] = acc;
    }

    float2* soA = (float2*)&uni.ob[(r * T_SEQ + tA) * VCB];
    float2* soB = (float2*)&uni.ob[(r * T_SEQ + tB) * VCB];
#pragma unroll
    for (int v = 0; v < VCB; v += 2) {
        u64 acc0 = f2mul(z[0], cw(27 + v * 3 + 0));
        u64 acc1 = f2mul(z[0], cw(27 + (v + 1) * 3 + 0));
        acc0 = f2fma(z[1], cw(27 + v * 3 + 1), acc0);
        acc1 = f2fma(z[1], cw(27 + (v + 1) * 3 + 1), acc1);
        acc0 = f2fma(z[2], cw(27 + v * 3 + 2), acc0);
        acc1 = f2fma(z[2], cw(27 + (v + 1) * 3 + 2), acc1);
        float a0, b0, a1, b1;
        up2(acc0, a0, b0); up2(acc1, a1, b1);
        soA[v / 2] = make_float2(a0, a1);
        soB[v / 2] = make_float2(b0, b1);
    }
    __syncthreads();

    // coalesced block-contiguous output write
    float4* dst = (float4*)(out + (size_t)blockIdx.x * (RWS * T_SEQ * VCB));
    const float4* src = (const float4*)uni.ob;
#pragma unroll
    for (int i = tid; i < (RWS * T_SEQ * VCB) / 4; i += NT) dst[i] = src[i];
}

extern "C" void kernel_launch(void* const* d_in, const int* in_sizes, int n_in,
                              void* d_out, int out_size) {
    const int* idx = (const int*)d_in[0];
    const float* tok_emb = (const float*)d_in[1];
    const float* pos_enc = (const float*)d_in[2];
    const float* q_w = (const float*)d_in[3];
    const float* k_w = (const float*)d_in[4];
    const float* v_w = (const float*)d_in[5];
    const float* out_w = (const float*)d_in[6];
    const float* ln1_g = (const float*)d_in[7];
    const float* ln1_b = (const float*)d_in[8];
    const float* ln2_g = (const float*)d_in[9];
    const float* ln2_b = (const float*)d_in[10];
    const float* lnf_g = (const float*)d_in[11];
    const float* lnf_b = (const float*)d_in[12];
    const float* ffn_w1 = (const float*)d_in[13];
    const float* ffn_b1 = (const float*)d_in[14];
    const float* ffn_w2 = (const float*)d_in[15];
    const float* ffn_b2 = (const float*)d_in[16];
    const float* head_w = (const float*)d_in[17];
    float* out = (float*)d_out;

    prep_kernel<<<1, 192>>>(tok_emb, q_w, k_w, v_w, out_w,
                            ln1_g, ln1_b, ln2_g, ln2_b, lnf_g, lnf_b,
                            ffn_w1, ffn_b1, ffn_w2, ffn_b2, head_w);

    void* scratch_ptr = nullptr;
    cudaGetSymbolAddress(&scratch_ptr, g_scratch);
    cudaMemcpyToSymbolAsync(c_pack, scratch_ptr, NPK * sizeof(float2), 0,
                            cudaMemcpyDeviceToDevice, 0);

    const int B = in_sizes[0] / T_SEQ;   // 65536
    dim3 block(RWS, TH);
    dim3 grid(B / RWS);
    add_tf_kernel<<<grid, block>>>(idx, tok_emb, pos_enc, out);
}